// round 3
// baseline (speedup 1.0000x reference)
#include <cuda_runtime.h>

#define NVOX (128*128*128)
#define NBATCH 2
#define NTHREADS (NBATCH*NVOX)
#define INT_STEPS 7

#define TS   16                 // tile size per dim
#define HALO 2
#define ES   (TS + 2*HALO)      // 20
#define SVOL (ES*ES*ES)         // 8000
#define SMEM_BYTES (3*SVOL*4)   // 96000

#define PAD 8
// SoA scratch: [b][c][z][y][x], padded front/back for unclamped x-spill reads.
__device__ float g_rawA[NBATCH*3*NVOX + 2*PAD];
__device__ float g_rawB[NBATCH*3*NVOX + 2*PAD];

// ---------------------------------------------------------------------------
// v0 = vel/128, packed [b,z,y,x,3] -> SoA [b][c][vox]
// ---------------------------------------------------------------------------
__global__ void __launch_bounds__(512)
scale_soa_kernel(const float* __restrict__ in, float* __restrict__ out) {
    int i = blockIdx.x * blockDim.x + threadIdx.x;    // voxel id (0..NTHREADS)
    const float s = 1.0f / 128.0f;
    int b = i >> 21;
    int vox = i & (NVOX - 1);
    float v0 = in[i * 3 + 0] * s;
    float v1 = in[i * 3 + 1] * s;
    float v2 = in[i * 3 + 2] * s;
    float* ob = out + b * 3 * NVOX;
    ob[0 * NVOX + vox] = v0;
    ob[1 * NVOX + vox] = v1;
    ob[2 * NVOX + vox] = v2;
}

// nested trilinear lerp over 8 pre-gathered corners
__device__ __forceinline__ float lerp8(float c000, float c001, float c010, float c011,
                                       float c100, float c101, float c110, float c111,
                                       float wx, float wy, float wz) {
    float a00 = fmaf(wx, c001 - c000, c000);
    float a01 = fmaf(wx, c011 - c010, c010);
    float a10 = fmaf(wx, c101 - c100, c100);
    float a11 = fmaf(wx, c111 - c110, c110);
    float b0 = fmaf(wy, a01 - a00, a00);
    float b1 = fmaf(wy, a11 - a10, a10);
    return fmaf(wz, b1 - b0, b0);
}

// ---------------------------------------------------------------------------
// One scaling-and-squaring step over a 16^3 tile with halo-2 smem neighborhood.
// ---------------------------------------------------------------------------
template<bool FINAL>
__global__ void __launch_bounds__(512, 2)
step_tile_kernel(const float* __restrict__ src, float* __restrict__ dst) {
    extern __shared__ float sm[];
    float* s0 = sm;
    float* s1 = sm + SVOL;
    float* s2 = sm + 2 * SVOL;

    int tid = threadIdx.x;
    int bz = blockIdx.z & 7;
    int b  = blockIdx.z >> 3;
    int ox = blockIdx.x << 4, oy = blockIdx.y << 4, oz = bz << 4;
    int hx = ox - HALO, hy = oy - HALO, hz = oz - HALO;

    const float* src_b = src + b * 3 * NVOX;

    // ---- cooperative halo load: 3 channels x 400 rows x 10 float2 = 12000 ops
    for (int i = tid; i < 3 * ES * ES * (ES / 2); i += 512) {
        int ch  = i / (ES * ES * (ES / 2));        // / 4000
        int rem = i - ch * (ES * ES * (ES / 2));
        int row = rem / (ES / 2);                  // 0..399  (= lz*ES + ly)
        int j   = rem - row * (ES / 2);            // float2 index in row
        int lz  = row / ES;
        int ly  = row - lz * ES;
        int gz = min(max(hz + lz, 0), 127);
        int gy = min(max(hy + ly, 0), 127);
        int gbase = ((gz << 7) + gy) << 7;
        float2 v = *(const float2*)(src_b + ch * NVOX + gbase + hx + j * 2);
        float* sc = sm + ch * SVOL + row * ES + j * 2;
        sc[0] = v.x;
        sc[1] = v.y;
    }
    __syncthreads();

    // ---- 8 outputs per thread
    #pragma unroll 2
    for (int k = 0; k < 8; k++) {
        int idx = tid + (k << 9);                  // 0..4095
        int lx = idx & 15, ly = (idx >> 4) & 15, lz = idx >> 8;
        int x = ox + lx, y = oy + ly, z = oz + lz;

        int sown = ((lz + HALO) * ES + (ly + HALO)) * ES + (lx + HALO);
        float vz = s0[sown];
        float vy = s1[sown];
        float vx = s2[sown];

        float lzc = fminf(fmaxf((float)z + vz, 0.0f), 127.0f);
        float lyc = fminf(fmaxf((float)y + vy, 0.0f), 127.0f);
        float lxc = fminf(fmaxf((float)x + vx, 0.0f), 127.0f);

        float fz = floorf(lzc), fy = floorf(lyc), fx = floorf(lxc);
        int iz0 = (int)fz, iy0 = (int)fy, ix0 = (int)fx;
        int iz1 = min(iz0 + 1, 127);
        int iy1 = min(iy0 + 1, 127);
        int ix1 = min(ix0 + 1, 127);
        float wz = lzc - fz, wy = lyc - fy, wx = lxc - fx;

        int pz0 = iz0 - hz, py0 = iy0 - hy, px0 = ix0 - hx;

        float rz, ry, rx;
        bool in_tile = ((unsigned)px0 <= (ES - 2)) &
                       ((unsigned)py0 <= (ES - 2)) &
                       ((unsigned)pz0 <= (ES - 2));
        if (__builtin_expect(in_tile, 1)) {
            int pz1 = iz1 - hz, py1 = iy1 - hy, px1 = ix1 - hx;
            int r00 = (pz0 * ES + py0) * ES;
            int r01 = (pz0 * ES + py1) * ES;
            int r10 = (pz1 * ES + py0) * ES;
            int r11 = (pz1 * ES + py1) * ES;
            int o000 = r00 + px0, o001 = r00 + px1;
            int o010 = r01 + px0, o011 = r01 + px1;
            int o100 = r10 + px0, o101 = r10 + px1;
            int o110 = r11 + px0, o111 = r11 + px1;
            rz = lerp8(s0[o000], s0[o001], s0[o010], s0[o011],
                       s0[o100], s0[o101], s0[o110], s0[o111], wx, wy, wz);
            ry = lerp8(s1[o000], s1[o001], s1[o010], s1[o011],
                       s1[o100], s1[o101], s1[o110], s1[o111], wx, wy, wz);
            rx = lerp8(s2[o000], s2[o001], s2[o010], s2[o011],
                       s2[o100], s2[o101], s2[o110], s2[o111], wx, wy, wz);
        } else {
            // exact global fallback (rare outliers)
            int g00 = (((iz0 << 7) + iy0) << 7);
            int g01 = (((iz0 << 7) + iy1) << 7);
            int g10 = (((iz1 << 7) + iy0) << 7);
            int g11 = (((iz1 << 7) + iy1) << 7);
            int o000 = g00 + ix0, o001 = g00 + ix1;
            int o010 = g01 + ix0, o011 = g01 + ix1;
            int o100 = g10 + ix0, o101 = g10 + ix1;
            int o110 = g11 + ix0, o111 = g11 + ix1;
            const float* p0 = src_b;
            const float* p1 = src_b + NVOX;
            const float* p2 = src_b + 2 * NVOX;
            rz = lerp8(__ldg(p0 + o000), __ldg(p0 + o001), __ldg(p0 + o010), __ldg(p0 + o011),
                       __ldg(p0 + o100), __ldg(p0 + o101), __ldg(p0 + o110), __ldg(p0 + o111),
                       wx, wy, wz);
            ry = lerp8(__ldg(p1 + o000), __ldg(p1 + o001), __ldg(p1 + o010), __ldg(p1 + o011),
                       __ldg(p1 + o100), __ldg(p1 + o101), __ldg(p1 + o110), __ldg(p1 + o111),
                       wx, wy, wz);
            rx = lerp8(__ldg(p2 + o000), __ldg(p2 + o001), __ldg(p2 + o010), __ldg(p2 + o011),
                       __ldg(p2 + o100), __ldg(p2 + o101), __ldg(p2 + o110), __ldg(p2 + o111),
                       wx, wy, wz);
        }

        float resz = vz + rz;
        float resy = vy + ry;
        float resx = vx + rx;

        int vox = (((z << 7) + y) << 7) + x;
        if (FINAL) {
            float* o = dst + (size_t)(b * NVOX + vox) * 3;
            o[0] = resz;
            o[1] = resy;
            o[2] = resx;
        } else {
            float* db = dst + b * 3 * NVOX;
            db[0 * NVOX + vox] = resz;
            db[1 * NVOX + vox] = resy;
            db[2 * NVOX + vox] = resx;
        }
    }
}

// ---------------------------------------------------------------------------
extern "C" void kernel_launch(void* const* d_in, const int* in_sizes, int n_in,
                              void* d_out, int out_size) {
    const float* vel = (const float*)d_in[0];
    float* out = (float*)d_out;

    float *rawA = nullptr, *rawB = nullptr;
    cudaGetSymbolAddress((void**)&rawA, g_rawA);
    cudaGetSymbolAddress((void**)&rawB, g_rawB);
    float* A = rawA + PAD;
    float* B = rawB + PAD;

    cudaFuncSetAttribute(step_tile_kernel<false>,
                         cudaFuncAttributeMaxDynamicSharedMemorySize, SMEM_BYTES);
    cudaFuncSetAttribute(step_tile_kernel<true>,
                         cudaFuncAttributeMaxDynamicSharedMemorySize, SMEM_BYTES);

    // v0 = vel/128 in SoA layout -> A
    scale_soa_kernel<<<NTHREADS / 512, 512>>>(vel, A);

    dim3 grid(8, 8, 16);   // 8x8x8 tiles x 2 batches
    const float* src = A;
    float* dst = B;
    for (int s = 0; s < INT_STEPS - 1; s++) {
        step_tile_kernel<false><<<grid, 512, SMEM_BYTES>>>(src, dst);
        const float* t = dst;
        dst = (float*)src;
        src = t;
    }
    step_tile_kernel<true><<<grid, 512, SMEM_BYTES>>>(src, out);
}

// round 4
// speedup vs baseline: 1.4171x; 1.4171x over previous
#include <cuda_runtime.h>

#define NVOX (128*128*128)
#define NBATCH 2
#define NTHREADS (NBATCH*NVOX)
#define INT_STEPS 7

// Max constant-offset spill past the last valid element: 16384+128+1 = 16513.
// Pad tail with zeros (static __device__ arrays are zero-initialized) so the
// spill reads finite values that are then multiplied by an exact 0 weight.
#define TAILPAD 16896
__device__ float g_bufA[NBATCH*3*NVOX + TAILPAD];
__device__ float g_bufB[NBATCH*3*NVOX + TAILPAD];

// ---------------------------------------------------------------------------
// v0 = vel/128, packed [b,z,y,x,3] -> SoA [b][c][vox]
// ---------------------------------------------------------------------------
__global__ void __launch_bounds__(256)
scale_soa_kernel(const float* __restrict__ in, float* __restrict__ out) {
    int i = blockIdx.x * blockDim.x + threadIdx.x;
    const float s = 1.0f / 128.0f;
    int b = i >> 21;
    int vox = i & (NVOX - 1);
    float v0 = in[i * 3 + 0] * s;
    float v1 = in[i * 3 + 1] * s;
    float v2 = in[i * 3 + 2] * s;
    float* ob = out + b * 3 * NVOX;
    ob[0 * NVOX + vox] = v0;
    ob[1 * NVOX + vox] = v1;
    ob[2 * NVOX + vox] = v2;
}

// Trilinear over 8 corners at constant offsets from g (immediate-offset LDGs).
__device__ __forceinline__ float gather_lerp(const float* __restrict__ g,
                                             float wx, float wy, float wz) {
    float c000 = __ldg(g + 0),           c001 = __ldg(g + 1);
    float c010 = __ldg(g + 128),         c011 = __ldg(g + 129);
    float c100 = __ldg(g + 16384),       c101 = __ldg(g + 16385);
    float c110 = __ldg(g + 16384 + 128), c111 = __ldg(g + 16384 + 129);
    float a00 = fmaf(wx, c001 - c000, c000);
    float a01 = fmaf(wx, c011 - c010, c010);
    float a10 = fmaf(wx, c101 - c100, c100);
    float a11 = fmaf(wx, c111 - c110, c110);
    float b0 = fmaf(wy, a01 - a00, a00);
    float b1 = fmaf(wy, a11 - a10, a10);
    return fmaf(wz, b1 - b0, b0);
}

// ---------------------------------------------------------------------------
// One step: vout = vin + trilerp(vin, grid + vin).  SoA in, SoA (or packed) out.
// ---------------------------------------------------------------------------
template<bool FINAL>
__global__ void __launch_bounds__(256)
step_kernel(const float* __restrict__ src, float* __restrict__ dst) {
    int idx = blockIdx.x * blockDim.x + threadIdx.x;   // 0..NTHREADS-1
    int x = idx & 127;
    int y = (idx >> 7) & 127;
    int z = (idx >> 14) & 127;
    int b = idx >> 21;
    int vox = idx & (NVOX - 1);

    const float* sb = src + b * 3 * NVOX;
    float vz = __ldg(sb + 0 * NVOX + vox);
    float vy = __ldg(sb + 1 * NVOX + vox);
    float vx = __ldg(sb + 2 * NVOX + vox);

    // absolute sample coords, clipped to [0,127]
    float lz = fminf(fmaxf((float)z + vz, 0.0f), 127.0f);
    float ly = fminf(fmaxf((float)y + vy, 0.0f), 127.0f);
    float lx = fminf(fmaxf((float)x + vx, 0.0f), 127.0f);

    float fz = floorf(lz), fy = floorf(ly), fx = floorf(lx);
    float wz = lz - fz, wy = ly - fy, wx = lx - fx;
    // i1 clamp elided: whenever i0 == 127 the weight is exactly 0 and the
    // +1/+128/+16384 spill reads finite in-buffer or zero-pad data.
    int o000 = ((((int)fz << 7) + (int)fy) << 7) + (int)fx;

    const float* g0 = sb + o000;
    float rz = vz + gather_lerp(g0,            wx, wy, wz);
    float ry = vy + gather_lerp(g0 + NVOX,     wx, wy, wz);
    float rx = vx + gather_lerp(g0 + 2 * NVOX, wx, wy, wz);

    if (FINAL) {
        float* o = dst + (size_t)idx * 3;
        o[0] = rz; o[1] = ry; o[2] = rx;
    } else {
        float* db = dst + b * 3 * NVOX;
        db[0 * NVOX + vox] = rz;
        db[1 * NVOX + vox] = ry;
        db[2 * NVOX + vox] = rx;
    }
}

// ---------------------------------------------------------------------------
extern "C" void kernel_launch(void* const* d_in, const int* in_sizes, int n_in,
                              void* d_out, int out_size) {
    const float* vel = (const float*)d_in[0];
    float* out = (float*)d_out;

    float *A = nullptr, *B = nullptr;
    cudaGetSymbolAddress((void**)&A, g_bufA);
    cudaGetSymbolAddress((void**)&B, g_bufB);

    const int nblocks = NTHREADS / 256;

    scale_soa_kernel<<<nblocks, 256>>>(vel, A);

    const float* src = A;
    float* dst = B;
    for (int s = 0; s < INT_STEPS - 1; s++) {
        step_kernel<false><<<nblocks, 256>>>(src, dst);
        const float* t = dst;
        dst = (float*)src;
        src = t;
    }
    step_kernel<true><<<nblocks, 256>>>(src, out);
}

// round 5
// speedup vs baseline: 1.4657x; 1.0343x over previous
#include <cuda_runtime.h>

#define NVOX (128*128*128)
#define NBATCH 2
#define NTHREADS (NBATCH*NVOX)
#define INT_STEPS 7

// Max constant-offset spill past the last valid voxel: 16384+128+1 = 16513 voxels.
// Tail-pad with zeros (static __device__ arrays are zero-initialized); the spilled
// reads are always multiplied by an exact 0.0 weight (clip => frac == 0).
#define TAILPAD 16640

// (z,y) channels packed as float2 per voxel; x channel scalar. Ping-pong pairs.
__device__ float2 g_zyA[NBATCH*NVOX + TAILPAD];
__device__ float2 g_zyB[NBATCH*NVOX + TAILPAD];
__device__ float  g_xA [NBATCH*NVOX + TAILPAD];
__device__ float  g_xB [NBATCH*NVOX + TAILPAD];

// ---------------------------------------------------------------------------
// v0 = vel/128, packed [b,z,y,x,3] -> zy float2 + x float
// ---------------------------------------------------------------------------
__global__ void __launch_bounds__(256)
scale_pack_kernel(const float* __restrict__ in,
                  float2* __restrict__ zy, float* __restrict__ xb) {
    int i = blockIdx.x * blockDim.x + threadIdx.x;
    const float s = 1.0f / 128.0f;
    float v0 = in[i * 3 + 0] * s;
    float v1 = in[i * 3 + 1] * s;
    float v2 = in[i * 3 + 2] * s;
    zy[i] = make_float2(v0, v1);
    xb[i] = v2;
}

// ---------------------------------------------------------------------------
// Trilinear gathers at compile-time constant offsets from the cell base.
// ---------------------------------------------------------------------------
__device__ __forceinline__ float2 gather_lerp2(const float2* __restrict__ g,
                                               float wx, float wy, float wz) {
    float2 c000 = __ldg(g + 0),     c001 = __ldg(g + 1);
    float2 c010 = __ldg(g + 128),   c011 = __ldg(g + 129);
    float2 c100 = __ldg(g + 16384), c101 = __ldg(g + 16385);
    float2 c110 = __ldg(g + 16512), c111 = __ldg(g + 16513);
    float a00x = fmaf(wx, c001.x - c000.x, c000.x);
    float a00y = fmaf(wx, c001.y - c000.y, c000.y);
    float a01x = fmaf(wx, c011.x - c010.x, c010.x);
    float a01y = fmaf(wx, c011.y - c010.y, c010.y);
    float a10x = fmaf(wx, c101.x - c100.x, c100.x);
    float a10y = fmaf(wx, c101.y - c100.y, c100.y);
    float a11x = fmaf(wx, c111.x - c110.x, c110.x);
    float a11y = fmaf(wx, c111.y - c110.y, c110.y);
    float b0x = fmaf(wy, a01x - a00x, a00x);
    float b0y = fmaf(wy, a01y - a00y, a00y);
    float b1x = fmaf(wy, a11x - a10x, a10x);
    float b1y = fmaf(wy, a11y - a10y, a10y);
    return make_float2(fmaf(wz, b1x - b0x, b0x), fmaf(wz, b1y - b0y, b0y));
}

__device__ __forceinline__ float gather_lerp1(const float* __restrict__ g,
                                              float wx, float wy, float wz) {
    float c000 = __ldg(g + 0),     c001 = __ldg(g + 1);
    float c010 = __ldg(g + 128),   c011 = __ldg(g + 129);
    float c100 = __ldg(g + 16384), c101 = __ldg(g + 16385);
    float c110 = __ldg(g + 16512), c111 = __ldg(g + 16513);
    float a00 = fmaf(wx, c001 - c000, c000);
    float a01 = fmaf(wx, c011 - c010, c010);
    float a10 = fmaf(wx, c101 - c100, c100);
    float a11 = fmaf(wx, c111 - c110, c110);
    float b0 = fmaf(wy, a01 - a00, a00);
    float b1 = fmaf(wy, a11 - a10, a10);
    return fmaf(wz, b1 - b0, b0);
}

// ---------------------------------------------------------------------------
// One step: v <- v + trilerp(v, grid + v)
// ---------------------------------------------------------------------------
template<bool FINAL>
__global__ void __launch_bounds__(256)
step_kernel(const float2* __restrict__ src_zy, const float* __restrict__ src_x,
            float2* __restrict__ dst_zy, float* __restrict__ dst_x,
            float* __restrict__ out) {
    int idx = blockIdx.x * blockDim.x + threadIdx.x;   // 0..NTHREADS-1
    int x = idx & 127;
    int y = (idx >> 7) & 127;
    int z = (idx >> 14) & 127;
    int b = idx >> 21;
    int vox = idx & (NVOX - 1);

    const float2* zb = src_zy + b * NVOX;
    const float*  xbp = src_x + b * NVOX;
    float2 vzy = __ldg(zb + vox);
    float  vx  = __ldg(xbp + vox);

    float lz = fminf(fmaxf((float)z + vzy.x, 0.0f), 127.0f);
    float ly = fminf(fmaxf((float)y + vzy.y, 0.0f), 127.0f);
    float lx = fminf(fmaxf((float)x + vx,    0.0f), 127.0f);

    float fz = floorf(lz), fy = floorf(ly), fx = floorf(lx);
    float wz = lz - fz, wy = ly - fy, wx = lx - fx;
    // i1 clamp elided: when i0 == 127 the weight is exactly 0 and the
    // +1/+128/+16384 spill reads finite in-buffer or zero-pad data.
    int o000 = ((((int)fz << 7) + (int)fy) << 7) + (int)fx;

    float2 rzy = gather_lerp2(zb + o000, wx, wy, wz);
    float  rx  = gather_lerp1(xbp + o000, wx, wy, wz);

    float resz = vzy.x + rzy.x;
    float resy = vzy.y + rzy.y;
    float resx = vx + rx;

    if (FINAL) {
        float* o = out + (size_t)idx * 3;
        o[0] = resz; o[1] = resy; o[2] = resx;
    } else {
        dst_zy[b * NVOX + vox] = make_float2(resz, resy);
        dst_x [b * NVOX + vox] = resx;
    }
}

// ---------------------------------------------------------------------------
extern "C" void kernel_launch(void* const* d_in, const int* in_sizes, int n_in,
                              void* d_out, int out_size) {
    const float* vel = (const float*)d_in[0];
    float* out = (float*)d_out;

    float2 *zyA = nullptr, *zyB = nullptr;
    float  *xA = nullptr,  *xB = nullptr;
    cudaGetSymbolAddress((void**)&zyA, g_zyA);
    cudaGetSymbolAddress((void**)&zyB, g_zyB);
    cudaGetSymbolAddress((void**)&xA,  g_xA);
    cudaGetSymbolAddress((void**)&xB,  g_xB);

    const int nblocks = NTHREADS / 256;

    scale_pack_kernel<<<nblocks, 256>>>(vel, zyA, xA);

    const float2* szy = zyA; const float* sx = xA;
    float2* dzy = zyB;       float* dx = xB;
    for (int s = 0; s < INT_STEPS - 1; s++) {
        step_kernel<false><<<nblocks, 256>>>(szy, sx, dzy, dx, nullptr);
        const float2* t2 = dzy; dzy = (float2*)szy; szy = t2;
        const float*  t1 = dx;  dx  = (float*)sx;   sx  = t1;
    }
    step_kernel<true><<<nblocks, 256>>>(szy, sx, nullptr, nullptr, out);
}

// round 6
// speedup vs baseline: 1.5607x; 1.0648x over previous
#include <cuda_runtime.h>
#include <cuda_fp16.h>

#define NVOX (128*128*128)
#define NBATCH 2
#define NTHREADS (NBATCH*NVOX)
#define INT_STEPS 7

// Max constant-offset spill past the last valid voxel: 16384+128+1 voxels.
// Tail-pad with zeros (static __device__ arrays are zero-initialized); spilled
// reads are always multiplied by an exact 0.0 weight (clip => frac == 0).
#define TAILPAD 16640

// fp32 state (exact accumulation), ping-pong
__device__ float2 g_zyA[NBATCH*NVOX + TAILPAD];
__device__ float2 g_zyB[NBATCH*NVOX + TAILPAD];
__device__ float  g_xA [NBATCH*NVOX + TAILPAD];
__device__ float  g_xB [NBATCH*NVOX + TAILPAD];
// fp16 gather mirrors, ping-pong
__device__ __half2 g_mzyA[NBATCH*NVOX + TAILPAD];
__device__ __half2 g_mzyB[NBATCH*NVOX + TAILPAD];
__device__ __half  g_mxA [NBATCH*NVOX + TAILPAD];
__device__ __half  g_mxB [NBATCH*NVOX + TAILPAD];

// ---------------------------------------------------------------------------
// v0 = vel/128, packed [b,z,y,x,3] -> fp32 state + fp16 mirror
// ---------------------------------------------------------------------------
__global__ void __launch_bounds__(256)
scale_pack_kernel(const float* __restrict__ in,
                  float2* __restrict__ zy, float* __restrict__ xb,
                  __half2* __restrict__ mzy, __half* __restrict__ mx) {
    int i = blockIdx.x * blockDim.x + threadIdx.x;
    const float s = 1.0f / 128.0f;
    float v0 = in[i * 3 + 0] * s;
    float v1 = in[i * 3 + 1] * s;
    float v2 = in[i * 3 + 2] * s;
    zy[i] = make_float2(v0, v1);
    xb[i] = v2;
    mzy[i] = __floats2half2_rn(v0, v1);
    mx[i]  = __float2half_rn(v2);
}

// ---------------------------------------------------------------------------
// Trilinear gathers at compile-time constant offsets from the cell base,
// reading the fp16 mirror.
// ---------------------------------------------------------------------------
__device__ __forceinline__ float2 gather_lerp_h2(const __half2* __restrict__ g,
                                                 float wx, float wy, float wz) {
    float2 c000 = __half22float2(__ldg(g + 0));
    float2 c001 = __half22float2(__ldg(g + 1));
    float2 c010 = __half22float2(__ldg(g + 128));
    float2 c011 = __half22float2(__ldg(g + 129));
    float2 c100 = __half22float2(__ldg(g + 16384));
    float2 c101 = __half22float2(__ldg(g + 16385));
    float2 c110 = __half22float2(__ldg(g + 16512));
    float2 c111 = __half22float2(__ldg(g + 16513));
    float a00x = fmaf(wx, c001.x - c000.x, c000.x);
    float a00y = fmaf(wx, c001.y - c000.y, c000.y);
    float a01x = fmaf(wx, c011.x - c010.x, c010.x);
    float a01y = fmaf(wx, c011.y - c010.y, c010.y);
    float a10x = fmaf(wx, c101.x - c100.x, c100.x);
    float a10y = fmaf(wx, c101.y - c100.y, c100.y);
    float a11x = fmaf(wx, c111.x - c110.x, c110.x);
    float a11y = fmaf(wx, c111.y - c110.y, c110.y);
    float b0x = fmaf(wy, a01x - a00x, a00x);
    float b0y = fmaf(wy, a01y - a00y, a00y);
    float b1x = fmaf(wy, a11x - a10x, a10x);
    float b1y = fmaf(wy, a11y - a10y, a10y);
    return make_float2(fmaf(wz, b1x - b0x, b0x), fmaf(wz, b1y - b0y, b0y));
}

__device__ __forceinline__ float gather_lerp_h1(const __half* __restrict__ g,
                                                float wx, float wy, float wz) {
    float c000 = __half2float(__ldg(g + 0));
    float c001 = __half2float(__ldg(g + 1));
    float c010 = __half2float(__ldg(g + 128));
    float c011 = __half2float(__ldg(g + 129));
    float c100 = __half2float(__ldg(g + 16384));
    float c101 = __half2float(__ldg(g + 16385));
    float c110 = __half2float(__ldg(g + 16512));
    float c111 = __half2float(__ldg(g + 16513));
    float a00 = fmaf(wx, c001 - c000, c000);
    float a01 = fmaf(wx, c011 - c010, c010);
    float a10 = fmaf(wx, c101 - c100, c100);
    float a11 = fmaf(wx, c111 - c110, c110);
    float b0 = fmaf(wy, a01 - a00, a00);
    float b1 = fmaf(wy, a11 - a10, a10);
    return fmaf(wz, b1 - b0, b0);
}

// ---------------------------------------------------------------------------
// One step: v <- v + trilerp(v_fp16mirror, grid + v)
// ---------------------------------------------------------------------------
template<bool FINAL>
__global__ void __launch_bounds__(256)
step_kernel(const float2* __restrict__ src_zy, const float* __restrict__ src_x,
            const __half2* __restrict__ msrc_zy, const __half* __restrict__ msrc_x,
            float2* __restrict__ dst_zy, float* __restrict__ dst_x,
            __half2* __restrict__ mdst_zy, __half* __restrict__ mdst_x,
            float* __restrict__ out) {
    int idx = blockIdx.x * blockDim.x + threadIdx.x;   // 0..NTHREADS-1
    int x = idx & 127;
    int y = (idx >> 7) & 127;
    int z = (idx >> 14) & 127;
    int b = idx >> 21;
    int vox = idx & (NVOX - 1);

    float2 vzy = __ldg(src_zy + b * NVOX + vox);
    float  vx  = __ldg(src_x  + b * NVOX + vox);

    float lz = fminf(fmaxf((float)z + vzy.x, 0.0f), 127.0f);
    float ly = fminf(fmaxf((float)y + vzy.y, 0.0f), 127.0f);
    float lx = fminf(fmaxf((float)x + vx,    0.0f), 127.0f);

    float fz = floorf(lz), fy = floorf(ly), fx = floorf(lx);
    float wz = lz - fz, wy = ly - fy, wx = lx - fx;
    // i1 clamp elided: when i0 == 127 the weight is exactly 0 and the
    // +1/+128/+16384 spill reads finite in-buffer or zero-pad data.
    int o000 = ((((int)fz << 7) + (int)fy) << 7) + (int)fx;

    float2 rzy = gather_lerp_h2(msrc_zy + b * NVOX + o000, wx, wy, wz);
    float  rx  = gather_lerp_h1(msrc_x  + b * NVOX + o000, wx, wy, wz);

    float resz = vzy.x + rzy.x;
    float resy = vzy.y + rzy.y;
    float resx = vx + rx;

    if (FINAL) {
        float* o = out + (size_t)idx * 3;
        o[0] = resz; o[1] = resy; o[2] = resx;
    } else {
        int d = b * NVOX + vox;
        dst_zy[d] = make_float2(resz, resy);
        dst_x [d] = resx;
        mdst_zy[d] = __floats2half2_rn(resz, resy);
        mdst_x [d] = __float2half_rn(resx);
    }
}

// ---------------------------------------------------------------------------
extern "C" void kernel_launch(void* const* d_in, const int* in_sizes, int n_in,
                              void* d_out, int out_size) {
    const float* vel = (const float*)d_in[0];
    float* out = (float*)d_out;

    float2 *zyA, *zyB; float *xA, *xB;
    __half2 *mzyA, *mzyB; __half *mxA, *mxB;
    cudaGetSymbolAddress((void**)&zyA, g_zyA);
    cudaGetSymbolAddress((void**)&zyB, g_zyB);
    cudaGetSymbolAddress((void**)&xA,  g_xA);
    cudaGetSymbolAddress((void**)&xB,  g_xB);
    cudaGetSymbolAddress((void**)&mzyA, g_mzyA);
    cudaGetSymbolAddress((void**)&mzyB, g_mzyB);
    cudaGetSymbolAddress((void**)&mxA,  g_mxA);
    cudaGetSymbolAddress((void**)&mxB,  g_mxB);

    const int nblocks = NTHREADS / 256;

    scale_pack_kernel<<<nblocks, 256>>>(vel, zyA, xA, mzyA, mxA);

    const float2* szy = zyA; const float* sx = xA;
    const __half2* mszy = mzyA; const __half* msx = mxA;
    float2* dzy = zyB; float* dx = xB;
    __half2* mdzy = mzyB; __half* mdx = mxB;

    for (int s = 0; s < INT_STEPS - 1; s++) {
        step_kernel<false><<<nblocks, 256>>>(szy, sx, mszy, msx,
                                             dzy, dx, mdzy, mdx, nullptr);
        { const float2* t = dzy; dzy = (float2*)szy; szy = t; }
        { const float*  t = dx;  dx  = (float*)sx;   sx  = t; }
        { const __half2* t = mdzy; mdzy = (__half2*)mszy; mszy = t; }
        { const __half*  t = mdx;  mdx  = (__half*)msx;   msx  = t; }
    }
    step_kernel<true><<<nblocks, 256>>>(szy, sx, mszy, msx,
                                        nullptr, nullptr, nullptr, nullptr, out);
}

// round 7
// speedup vs baseline: 1.6984x; 1.0882x over previous
#include <cuda_runtime.h>
#include <cuda_fp16.h>

#define NVOX (128*128*128)
#define NBATCH 2
#define NTHREADS (NBATCH*NVOX)
#define INT_STEPS 7

// Max constant-offset spill past the last valid voxel: 16384+128+1 voxels.
// Tail-pad with zeros (static __device__ arrays are zero-initialized); spilled
// reads are always multiplied by an exact 0.0 weight (clip => frac == 0).
#define TAILPAD 16640

// fp32 state (exact accumulation), ping-pong
__device__ float2 g_zyA[NBATCH*NVOX + TAILPAD];
__device__ float2 g_zyB[NBATCH*NVOX + TAILPAD];
__device__ float  g_xA [NBATCH*NVOX + TAILPAD];
__device__ float  g_xB [NBATCH*NVOX + TAILPAD];
// fp16 gather mirror: half4 (z,y,x,0) packed as uint2 (8B aligned), ping-pong
__device__ uint2 g_mA[NBATCH*NVOX + TAILPAD];
__device__ uint2 g_mB[NBATCH*NVOX + TAILPAD];

__device__ __forceinline__ uint2 pack_h4(float z, float y, float x) {
    __half2 a = __floats2half2_rn(z, y);
    __half2 b = __floats2half2_rn(x, 0.0f);
    uint2 m;
    m.x = *(const unsigned int*)&a;
    m.y = *(const unsigned int*)&b;
    return m;
}

// ---------------------------------------------------------------------------
// v0 = vel/128, packed [b,z,y,x,3] -> fp32 state + half4 mirror
// ---------------------------------------------------------------------------
__global__ void __launch_bounds__(256)
scale_pack_kernel(const float* __restrict__ in,
                  float2* __restrict__ zy, float* __restrict__ xb,
                  uint2* __restrict__ m) {
    int i = blockIdx.x * blockDim.x + threadIdx.x;
    const float s = 1.0f / 128.0f;
    float v0 = in[i * 3 + 0] * s;
    float v1 = in[i * 3 + 1] * s;
    float v2 = in[i * 3 + 2] * s;
    zy[i] = make_float2(v0, v1);
    xb[i] = v2;
    m[i] = pack_h4(v0, v1, v2);
}

// Unpack one mirror voxel -> (z,y,x) floats
__device__ __forceinline__ float3 unpack_h4(uint2 m) {
    __half2 a = *(const __half2*)&m.x;
    __half2 b = *(const __half2*)&m.y;
    float2 zy = __half22float2(a);
    return make_float3(zy.x, zy.y, __half2float(__low2half(b)));
}

// ---------------------------------------------------------------------------
// Trilinear over 8 corners at compile-time constant offsets; one LDG.64 per
// corner fetches all 3 channels from the half4 mirror.
// ---------------------------------------------------------------------------
__device__ __forceinline__ float3 gather_lerp(const uint2* __restrict__ g,
                                              float wx, float wy, float wz) {
    float3 c000 = unpack_h4(__ldg(g + 0));
    float3 c001 = unpack_h4(__ldg(g + 1));
    float3 c010 = unpack_h4(__ldg(g + 128));
    float3 c011 = unpack_h4(__ldg(g + 129));
    float3 c100 = unpack_h4(__ldg(g + 16384));
    float3 c101 = unpack_h4(__ldg(g + 16385));
    float3 c110 = unpack_h4(__ldg(g + 16512));
    float3 c111 = unpack_h4(__ldg(g + 16513));

    float a00x = fmaf(wx, c001.x - c000.x, c000.x);
    float a00y = fmaf(wx, c001.y - c000.y, c000.y);
    float a00z = fmaf(wx, c001.z - c000.z, c000.z);
    float a01x = fmaf(wx, c011.x - c010.x, c010.x);
    float a01y = fmaf(wx, c011.y - c010.y, c010.y);
    float a01z = fmaf(wx, c011.z - c010.z, c010.z);
    float a10x = fmaf(wx, c101.x - c100.x, c100.x);
    float a10y = fmaf(wx, c101.y - c100.y, c100.y);
    float a10z = fmaf(wx, c101.z - c100.z, c100.z);
    float a11x = fmaf(wx, c111.x - c110.x, c110.x);
    float a11y = fmaf(wx, c111.y - c110.y, c110.y);
    float a11z = fmaf(wx, c111.z - c110.z, c110.z);

    float b0x = fmaf(wy, a01x - a00x, a00x);
    float b0y = fmaf(wy, a01y - a00y, a00y);
    float b0z = fmaf(wy, a01z - a00z, a00z);
    float b1x = fmaf(wy, a11x - a10x, a10x);
    float b1y = fmaf(wy, a11y - a10y, a10y);
    float b1z = fmaf(wy, a11z - a10z, a10z);

    return make_float3(fmaf(wz, b1x - b0x, b0x),
                       fmaf(wz, b1y - b0y, b0y),
                       fmaf(wz, b1z - b0z, b0z));
}

// ---------------------------------------------------------------------------
// One step: v <- v + trilerp(v_mirror, grid + v)
// ---------------------------------------------------------------------------
template<bool FINAL>
__global__ void __launch_bounds__(256)
step_kernel(const float2* __restrict__ src_zy, const float* __restrict__ src_x,
            const uint2* __restrict__ msrc,
            float2* __restrict__ dst_zy, float* __restrict__ dst_x,
            uint2* __restrict__ mdst,
            float* __restrict__ out) {
    int idx = blockIdx.x * blockDim.x + threadIdx.x;   // 0..NTHREADS-1
    int x = idx & 127;
    int y = (idx >> 7) & 127;
    int z = (idx >> 14) & 127;
    int b = idx >> 21;
    int vox = idx & (NVOX - 1);

    float2 vzy = __ldg(src_zy + b * NVOX + vox);
    float  vx  = __ldg(src_x  + b * NVOX + vox);

    float lz = fminf(fmaxf((float)z + vzy.x, 0.0f), 127.0f);
    float ly = fminf(fmaxf((float)y + vzy.y, 0.0f), 127.0f);
    float lx = fminf(fmaxf((float)x + vx,    0.0f), 127.0f);

    float fz = floorf(lz), fy = floorf(ly), fx = floorf(lx);
    float wz = lz - fz, wy = ly - fy, wx = lx - fx;
    // i1 clamp elided: when i0 == 127 the weight is exactly 0 and the
    // +1/+128/+16384 spill reads finite in-buffer or zero-pad data.
    int o000 = ((((int)fz << 7) + (int)fy) << 7) + (int)fx;

    float3 r = gather_lerp(msrc + b * NVOX + o000, wx, wy, wz);

    float resz = vzy.x + r.x;
    float resy = vzy.y + r.y;
    float resx = vx + r.z;

    if (FINAL) {
        float* o = out + (size_t)idx * 3;
        o[0] = resz; o[1] = resy; o[2] = resx;
    } else {
        int d = b * NVOX + vox;
        dst_zy[d] = make_float2(resz, resy);
        dst_x [d] = resx;
        mdst[d] = pack_h4(resz, resy, resx);
    }
}

// ---------------------------------------------------------------------------
extern "C" void kernel_launch(void* const* d_in, const int* in_sizes, int n_in,
                              void* d_out, int out_size) {
    const float* vel = (const float*)d_in[0];
    float* out = (float*)d_out;

    float2 *zyA, *zyB; float *xA, *xB; uint2 *mA, *mB;
    cudaGetSymbolAddress((void**)&zyA, g_zyA);
    cudaGetSymbolAddress((void**)&zyB, g_zyB);
    cudaGetSymbolAddress((void**)&xA,  g_xA);
    cudaGetSymbolAddress((void**)&xB,  g_xB);
    cudaGetSymbolAddress((void**)&mA,  g_mA);
    cudaGetSymbolAddress((void**)&mB,  g_mB);

    const int nblocks = NTHREADS / 256;

    scale_pack_kernel<<<nblocks, 256>>>(vel, zyA, xA, mA);

    const float2* szy = zyA; const float* sx = xA; const uint2* ms = mA;
    float2* dzy = zyB; float* dx = xB; uint2* md = mB;

    for (int s = 0; s < INT_STEPS - 1; s++) {
        step_kernel<false><<<nblocks, 256>>>(szy, sx, ms, dzy, dx, md, nullptr);
        { const float2* t = dzy; dzy = (float2*)szy; szy = t; }
        { const float*  t = dx;  dx  = (float*)sx;   sx  = t; }
        { const uint2*  t = md;  md  = (uint2*)ms;   ms  = t; }
    }
    step_kernel<true><<<nblocks, 256>>>(szy, sx, ms, nullptr, nullptr, nullptr, out);
}